// round 3
// baseline (speedup 1.0000x reference)
#include <cuda_runtime.h>
#include <math.h>

// Problem constants
#define Bb 4
#define Ss 2048
#define Ee 1024
#define Hh 512
#define NG 8          // B * 2 heads

// Tile config: 128x64 block tile, BK=16, 256 threads, 8x4 microtile
#define BM 128
#define BN 64
#define BK 16
#define PADF 4

// Scratch (static __device__ arrays: allocation-free per harness rules)
__device__ float g_Q[NG * Ss * Hh];
__device__ float g_K[NG * Ss * Hh];
__device__ float g_V[NG * Ss * Hh];
__device__ float g_Sc[(size_t)NG * Ss * Ss];
__device__ float g_O[Bb * Ss * Ee];

// Shared-tile compute: 16 k-steps, 8x4 accumulators.
#define COMPUTE_TILE(AsC, BsC)                                                  \
    _Pragma("unroll")                                                           \
    for (int k = 0; k < BK; k++) {                                              \
        float4 a0 = *(const float4*)&AsC[k][ty * 8];                            \
        float4 a1 = *(const float4*)&AsC[k][ty * 8 + 4];                        \
        float4 b  = *(const float4*)&BsC[k][tx * 4];                            \
        acc[0][0] += a0.x * b.x; acc[0][1] += a0.x * b.y; acc[0][2] += a0.x * b.z; acc[0][3] += a0.x * b.w; \
        acc[1][0] += a0.y * b.x; acc[1][1] += a0.y * b.y; acc[1][2] += a0.y * b.z; acc[1][3] += a0.y * b.w; \
        acc[2][0] += a0.z * b.x; acc[2][1] += a0.z * b.y; acc[2][2] += a0.z * b.z; acc[2][3] += a0.z * b.w; \
        acc[3][0] += a0.w * b.x; acc[3][1] += a0.w * b.y; acc[3][2] += a0.w * b.z; acc[3][3] += a0.w * b.w; \
        acc[4][0] += a1.x * b.x; acc[4][1] += a1.x * b.y; acc[4][2] += a1.x * b.z; acc[4][3] += a1.x * b.w; \
        acc[5][0] += a1.y * b.x; acc[5][1] += a1.y * b.y; acc[5][2] += a1.y * b.z; acc[5][3] += a1.y * b.w; \
        acc[6][0] += a1.z * b.x; acc[6][1] += a1.z * b.y; acc[6][2] += a1.z * b.z; acc[6][3] += a1.z * b.w; \
        acc[7][0] += a1.w * b.x; acc[7][1] += a1.w * b.y; acc[7][2] += a1.w * b.z; acc[7][3] += a1.w * b.w; \
    }

// ---------------------------------------------------------------------------
// Generic NT-GEMM body (A: M-rows k-contig lda, B: N-rows k-contig ldb),
// double-buffered. Used by qkv / scores / final via inlined copies.
// ---------------------------------------------------------------------------

// QKV projection
__global__ void qkv_kernel(const float* __restrict__ x,
                           const float* __restrict__ Wq, const float* __restrict__ bq,
                           const float* __restrict__ Wk, const float* __restrict__ bk,
                           const float* __restrict__ Wv, const float* __restrict__ bv)
{
    __shared__ float As[2][BK][BM + PADF];
    __shared__ float Bs[2][BK][BN + PADF];

    const int j   = blockIdx.z;
    const int mat = j >> 1;
    const int n   = j & 1;
    const int o0  = blockIdx.x * BN;
    const int m0  = blockIdx.y * BM;

    const float* W    = (mat == 0) ? Wq : (mat == 1) ? Wk : Wv;
    const float* bias = (mat == 0) ? bq : (mat == 1) ? bk : bv;
    float* out        = (mat == 0) ? g_Q : (mat == 1) ? g_K : g_V;

    const float* A  = x + (size_t)m0 * Ee + n * Hh;              // lda = Ee
    const float* Bm = W + (size_t)n * Hh * Hh + (size_t)o0 * Hh; // ldb = Hh

    const int tid = threadIdx.x;
    const int ty = tid >> 4, tx = tid & 15;
    const int lr = tid >> 2, lk = (tid & 3) * 4;   // A/B loads: row lr (and lr+64 for A)

    float acc[8][4] = {};

    // preload tile 0
    {
        float4 a0 = *(const float4*)(A + (size_t)lr * Ee + lk);
        float4 a1 = *(const float4*)(A + (size_t)(lr + 64) * Ee + lk);
        float4 b0 = *(const float4*)(Bm + (size_t)lr * Hh + lk);
        As[0][lk+0][lr] = a0.x; As[0][lk+1][lr] = a0.y; As[0][lk+2][lr] = a0.z; As[0][lk+3][lr] = a0.w;
        As[0][lk+0][lr+64] = a1.x; As[0][lk+1][lr+64] = a1.y; As[0][lk+2][lr+64] = a1.z; As[0][lk+3][lr+64] = a1.w;
        Bs[0][lk+0][lr] = b0.x; Bs[0][lk+1][lr] = b0.y; Bs[0][lk+2][lr] = b0.z; Bs[0][lk+3][lr] = b0.w;
    }
    __syncthreads();

    const int T = Hh / BK;
    int cur = 0;
    for (int t = 0; t < T; t++) {
        float4 pa0, pa1, pb;
        if (t + 1 < T) {
            int k0 = (t + 1) * BK;
            pa0 = *(const float4*)(A + (size_t)lr * Ee + k0 + lk);
            pa1 = *(const float4*)(A + (size_t)(lr + 64) * Ee + k0 + lk);
            pb  = *(const float4*)(Bm + (size_t)lr * Hh + k0 + lk);
        }
        COMPUTE_TILE(As[cur], Bs[cur]);
        if (t + 1 < T) {
            int nx = cur ^ 1;
            As[nx][lk+0][lr] = pa0.x; As[nx][lk+1][lr] = pa0.y; As[nx][lk+2][lr] = pa0.z; As[nx][lk+3][lr] = pa0.w;
            As[nx][lk+0][lr+64] = pa1.x; As[nx][lk+1][lr+64] = pa1.y; As[nx][lk+2][lr+64] = pa1.z; As[nx][lk+3][lr+64] = pa1.w;
            Bs[nx][lk+0][lr] = pb.x; Bs[nx][lk+1][lr] = pb.y; Bs[nx][lk+2][lr] = pb.z; Bs[nx][lk+3][lr] = pb.w;
            __syncthreads();
            cur = nx;
        }
    }

#pragma unroll
    for (int i = 0; i < 8; i++) {
        int m = m0 + ty * 8 + i;
        int b = m / Ss, s = m % Ss;
        size_t rowbase = ((size_t)(b * 2 + n) * Ss + s) * Hh;
#pragma unroll
        for (int jj = 0; jj < 4; jj++) {
            int o = o0 + tx * 4 + jj;
            out[rowbase + o] = acc[i][jj] + bias[n * Hh + o];
        }
    }
}

// scores: blocks with t0 >= s0+BM are fully above-diagonal -> skipped.
__global__ void scores_kernel(const int* __restrict__ maskedp)
{
    __shared__ float As[2][BK][BM + PADF];
    __shared__ float Bs[2][BK][BN + PADF];

    const int g  = blockIdx.z;
    const int t0 = blockIdx.x * BN;
    const int s0 = blockIdx.y * BM;
    const int masked = *maskedp;

    if (masked && t0 >= s0 + BM) return;

    float* out = g_Sc + (size_t)g * Ss * Ss;
    const float* A  = g_Q + (size_t)g * Ss * Hh + (size_t)s0 * Hh;  // lda = Hh
    const float* Bm = g_K + (size_t)g * Ss * Hh + (size_t)t0 * Hh;  // ldb = Hh

    const int tid = threadIdx.x;
    const int ty = tid >> 4, tx = tid & 15;
    const int lr = tid >> 2, lk = (tid & 3) * 4;

    float acc[8][4] = {};

    {
        float4 a0 = *(const float4*)(A + (size_t)lr * Hh + lk);
        float4 a1 = *(const float4*)(A + (size_t)(lr + 64) * Hh + lk);
        float4 b0 = *(const float4*)(Bm + (size_t)lr * Hh + lk);
        As[0][lk+0][lr] = a0.x; As[0][lk+1][lr] = a0.y; As[0][lk+2][lr] = a0.z; As[0][lk+3][lr] = a0.w;
        As[0][lk+0][lr+64] = a1.x; As[0][lk+1][lr+64] = a1.y; As[0][lk+2][lr+64] = a1.z; As[0][lk+3][lr+64] = a1.w;
        Bs[0][lk+0][lr] = b0.x; Bs[0][lk+1][lr] = b0.y; Bs[0][lk+2][lr] = b0.z; Bs[0][lk+3][lr] = b0.w;
    }
    __syncthreads();

    const int T = Hh / BK;
    int cur = 0;
    for (int t = 0; t < T; t++) {
        float4 pa0, pa1, pb;
        if (t + 1 < T) {
            int k0 = (t + 1) * BK;
            pa0 = *(const float4*)(A + (size_t)lr * Hh + k0 + lk);
            pa1 = *(const float4*)(A + (size_t)(lr + 64) * Hh + k0 + lk);
            pb  = *(const float4*)(Bm + (size_t)lr * Hh + k0 + lk);
        }
        COMPUTE_TILE(As[cur], Bs[cur]);
        if (t + 1 < T) {
            int nx = cur ^ 1;
            As[nx][lk+0][lr] = pa0.x; As[nx][lk+1][lr] = pa0.y; As[nx][lk+2][lr] = pa0.z; As[nx][lk+3][lr] = pa0.w;
            As[nx][lk+0][lr+64] = pa1.x; As[nx][lk+1][lr+64] = pa1.y; As[nx][lk+2][lr+64] = pa1.z; As[nx][lk+3][lr+64] = pa1.w;
            Bs[nx][lk+0][lr] = pb.x; Bs[nx][lk+1][lr] = pb.y; Bs[nx][lk+2][lr] = pb.z; Bs[nx][lk+3][lr] = pb.w;
            __syncthreads();
            cur = nx;
        }
    }

    const float scale = 0.044194173824159216f;  // 1/sqrt(512)
#pragma unroll
    for (int i = 0; i < 8; i++) {
        int s = s0 + ty * 8 + i;
#pragma unroll
        for (int jj = 0; jj < 4; jj++) {
            int tt = t0 + tx * 4 + jj;
            float v = acc[i][jj] * scale;
            if (masked && tt > s) v = -3.0e38f;
            out[(size_t)s * Ss + tt] = v;
        }
    }
}

// Row softmax. Causal limit rounds up to the BM=128 boundary so that pv's
// K-limit (s0+BM) only ever reads normalized zeros beyond column s.
__global__ void softmax_kernel(const int* __restrict__ maskedp)
{
    const int row = blockIdx.x;
    const int s = row & (Ss - 1);
    const int limit = (*maskedp) ? (((s >> 7) + 1) << 7) : Ss;

    float* r = g_Sc + (size_t)row * Ss;
    __shared__ float red[8];
    const int tid = threadIdx.x;           // 256 threads
    const int lane = tid & 31, warp = tid >> 5;

    float m = -3.4e38f;
    for (int i = tid; i < limit; i += 256) m = fmaxf(m, r[i]);
#pragma unroll
    for (int off = 16; off > 0; off >>= 1)
        m = fmaxf(m, __shfl_xor_sync(0xFFFFFFFFu, m, off));
    if (lane == 0) red[warp] = m;
    __syncthreads();
    if (warp == 0) {
        float v = (lane < 8) ? red[lane] : -3.4e38f;
#pragma unroll
        for (int off = 4; off > 0; off >>= 1)
            v = fmaxf(v, __shfl_xor_sync(0xFFFFFFFFu, v, off));
        if (lane == 0) red[0] = v;
    }
    __syncthreads();
    m = red[0];
    __syncthreads();

    float sum = 0.f;
    for (int i = tid; i < limit; i += 256) {
        float e = __expf(r[i] - m);
        r[i] = e;
        sum += e;
    }
#pragma unroll
    for (int off = 16; off > 0; off >>= 1)
        sum += __shfl_xor_sync(0xFFFFFFFFu, sum, off);
    if (lane == 0) red[warp] = sum;
    __syncthreads();
    if (warp == 0) {
        float v = (lane < 8) ? red[lane] : 0.f;
#pragma unroll
        for (int off = 4; off > 0; off >>= 1)
            v += __shfl_xor_sync(0xFFFFFFFFu, v, off);
        if (lane == 0) red[0] = v;
    }
    __syncthreads();
    float inv = 1.0f / red[0];
    for (int i = tid; i < limit; i += 256) r[i] *= inv;
}

// PV: NN GEMM (A = P rows k-contig, B = V n-contig), causal K-limit s0+BM.
__global__ void pv_kernel(const int* __restrict__ maskedp)
{
    __shared__ float As[2][BK][BM + PADF];
    __shared__ float Bs[2][BK][BN + PADF];

    const int g  = blockIdx.z;
    const int h0 = blockIdx.x * BN;
    const int s0 = blockIdx.y * BM;
    const int tid = threadIdx.x;

    const float* A  = g_Sc + (size_t)g * Ss * Ss + (size_t)s0 * Ss;  // lda = Ss
    const float* Bm = g_V + (size_t)g * Ss * Hh;                      // ldb = Hh

    const int kmax = (*maskedp) ? (s0 + BM) : Ss;

    const int ty = tid >> 4, tx = tid & 15;
    const int lr = tid >> 2, lk = (tid & 3) * 4;     // A load
    const int bk = tid >> 4, bn = (tid & 15) * 4;    // B load (n-contig)

    float acc[8][4] = {};

    {
        float4 a0 = *(const float4*)(A + (size_t)lr * Ss + lk);
        float4 a1 = *(const float4*)(A + (size_t)(lr + 64) * Ss + lk);
        As[0][lk+0][lr] = a0.x; As[0][lk+1][lr] = a0.y; As[0][lk+2][lr] = a0.z; As[0][lk+3][lr] = a0.w;
        As[0][lk+0][lr+64] = a1.x; As[0][lk+1][lr+64] = a1.y; As[0][lk+2][lr+64] = a1.z; As[0][lk+3][lr+64] = a1.w;
        float4 b0 = *(const float4*)(Bm + (size_t)bk * Hh + h0 + bn);
        *(float4*)&Bs[0][bk][bn] = b0;
    }
    __syncthreads();

    const int T = kmax / BK;
    int cur = 0;
    for (int t = 0; t < T; t++) {
        float4 pa0, pa1, pb;
        if (t + 1 < T) {
            int k0 = (t + 1) * BK;
            pa0 = *(const float4*)(A + (size_t)lr * Ss + k0 + lk);
            pa1 = *(const float4*)(A + (size_t)(lr + 64) * Ss + k0 + lk);
            pb  = *(const float4*)(Bm + (size_t)(k0 + bk) * Hh + h0 + bn);
        }
        COMPUTE_TILE(As[cur], Bs[cur]);
        if (t + 1 < T) {
            int nx = cur ^ 1;
            As[nx][lk+0][lr] = pa0.x; As[nx][lk+1][lr] = pa0.y; As[nx][lk+2][lr] = pa0.z; As[nx][lk+3][lr] = pa0.w;
            As[nx][lk+0][lr+64] = pa1.x; As[nx][lk+1][lr+64] = pa1.y; As[nx][lk+2][lr+64] = pa1.z; As[nx][lk+3][lr+64] = pa1.w;
            *(float4*)&Bs[nx][bk][bn] = pb;
            __syncthreads();
            cur = nx;
        }
    }

    const int b = g >> 1, n = g & 1;
#pragma unroll
    for (int i = 0; i < 8; i++) {
        int s = s0 + ty * 8 + i;
        size_t rowbase = ((size_t)b * Ss + s) * Ee + n * Hh;
#pragma unroll
        for (int jj = 0; jj < 4; jj++)
            g_O[rowbase + h0 + tx * 4 + jj] = acc[i][jj];
    }
}

// Final projection (NT)
__global__ void final_kernel(const float* __restrict__ Wf,
                             const float* __restrict__ bf,
                             float* __restrict__ y)
{
    __shared__ float As[2][BK][BM + PADF];
    __shared__ float Bs[2][BK][BN + PADF];

    const int o0 = blockIdx.x * BN;
    const int m0 = blockIdx.y * BM;
    const int tid = threadIdx.x;

    const float* A  = g_O + (size_t)m0 * Ee;   // lda = Ee
    const float* Bm = Wf + (size_t)o0 * Ee;    // ldb = Ee

    const int ty = tid >> 4, tx = tid & 15;
    const int lr = tid >> 2, lk = (tid & 3) * 4;

    float acc[8][4] = {};

    {
        float4 a0 = *(const float4*)(A + (size_t)lr * Ee + lk);
        float4 a1 = *(const float4*)(A + (size_t)(lr + 64) * Ee + lk);
        float4 b0 = *(const float4*)(Bm + (size_t)lr * Ee + lk);
        As[0][lk+0][lr] = a0.x; As[0][lk+1][lr] = a0.y; As[0][lk+2][lr] = a0.z; As[0][lk+3][lr] = a0.w;
        As[0][lk+0][lr+64] = a1.x; As[0][lk+1][lr+64] = a1.y; As[0][lk+2][lr+64] = a1.z; As[0][lk+3][lr+64] = a1.w;
        Bs[0][lk+0][lr] = b0.x; Bs[0][lk+1][lr] = b0.y; Bs[0][lk+2][lr] = b0.z; Bs[0][lk+3][lr] = b0.w;
    }
    __syncthreads();

    const int T = Ee / BK;
    int cur = 0;
    for (int t = 0; t < T; t++) {
        float4 pa0, pa1, pb;
        if (t + 1 < T) {
            int k0 = (t + 1) * BK;
            pa0 = *(const float4*)(A + (size_t)lr * Ee + k0 + lk);
            pa1 = *(const float4*)(A + (size_t)(lr + 64) * Ee + k0 + lk);
            pb  = *(const float4*)(Bm + (size_t)lr * Ee + k0 + lk);
        }
        COMPUTE_TILE(As[cur], Bs[cur]);
        if (t + 1 < T) {
            int nx = cur ^ 1;
            As[nx][lk+0][lr] = pa0.x; As[nx][lk+1][lr] = pa0.y; As[nx][lk+2][lr] = pa0.z; As[nx][lk+3][lr] = pa0.w;
            As[nx][lk+0][lr+64] = pa1.x; As[nx][lk+1][lr+64] = pa1.y; As[nx][lk+2][lr+64] = pa1.z; As[nx][lk+3][lr+64] = pa1.w;
            Bs[nx][lk+0][lr] = pb.x; Bs[nx][lk+1][lr] = pb.y; Bs[nx][lk+2][lr] = pb.z; Bs[nx][lk+3][lr] = pb.w;
            __syncthreads();
            cur = nx;
        }
    }

#pragma unroll
    for (int i = 0; i < 8; i++) {
        int m = m0 + ty * 8 + i;
#pragma unroll
        for (int jj = 0; jj < 4; jj++) {
            int o = o0 + tx * 4 + jj;
            y[(size_t)m * Ee + o] = acc[i][jj] + bf[o];
        }
    }
}

// ---------------------------------------------------------------------------
extern "C" void kernel_launch(void* const* d_in, const int* in_sizes, int n_in,
                              void* d_out, int out_size)
{
    const float* x  = (const float*)d_in[0];
    const float* Wq = (const float*)d_in[1];
    const float* bq = (const float*)d_in[2];
    const float* Wk = (const float*)d_in[3];
    const float* bk = (const float*)d_in[4];
    const float* Wv = (const float*)d_in[5];
    const float* bv = (const float*)d_in[6];
    const float* Wf = (const float*)d_in[7];
    const float* bf = (const float*)d_in[8];
    const int* masked = (const int*)d_in[9];
    float* y = (float*)d_out;

    const int M = Bb * Ss;  // 8192 tokens

    qkv_kernel<<<dim3(Hh / BN, M / BM, 6), 256>>>(x, Wq, bq, Wk, bk, Wv, bv);
    scores_kernel<<<dim3(Ss / BN, Ss / BM, NG), 256>>>(masked);
    softmax_kernel<<<NG * Ss, 256>>>(masked);
    pv_kernel<<<dim3(Hh / BN, Ss / BM, NG), 256>>>(masked);
    final_kernel<<<dim3(Ee / BN, M / BM), 256>>>(Wf, bf, y);
}

// round 6
// speedup vs baseline: 1.6135x; 1.6135x over previous
#include <cuda_runtime.h>
#include <math.h>
#include <stdint.h>

// Problem constants
#define Bb 4
#define Ss 2048
#define Ee 1024
#define Hh 512
#define NG 8          // B * 2 heads

// Tile config: 128x64 block tile, BK=16, 256 threads (8 warps: 4 M x 2 N)
#define BM 128
#define BN 64
#define BK 16
#define PADF 4

// Scratch
__device__ float g_Q[NG * Ss * Hh];
__device__ float g_K[NG * Ss * Hh];
__device__ float g_V[NG * Ss * Hh];
__device__ float g_Sc[(size_t)NG * Ss * Ss];
__device__ float g_O[Bb * Ss * Ee];

// fp32 -> tf32 (round-to-nearest) at smem-store time
__device__ __forceinline__ float f2tf32(float x) {
    asm("cvt.rna.tf32.f32 %0, %0;" : "+f"(x));
    return x;
}

// Tensor-core compute over one staged tile.
// Requires in scope: wm (0..3), wn (0..1), gid (lane>>2), tig (lane&3),
// float acc[2][4][4].
#define MMA_TILE(AsC, BsC)                                                     \
    _Pragma("unroll")                                                          \
    for (int ks = 0; ks < BK; ks += 8) {                                       \
        uint32_t af[2][4]; uint32_t bf2[4][2];                                 \
        _Pragma("unroll")                                                      \
        for (int mi = 0; mi < 2; mi++) {                                       \
            int mr = wm * 32 + mi * 16 + gid;                                  \
            af[mi][0] = __float_as_uint(AsC[ks + tig][mr]);                    \
            af[mi][1] = __float_as_uint(AsC[ks + tig][mr + 8]);                \
            af[mi][2] = __float_as_uint(AsC[ks + tig + 4][mr]);                \
            af[mi][3] = __float_as_uint(AsC[ks + tig + 4][mr + 8]);            \
        }                                                                      \
        _Pragma("unroll")                                                      \
        for (int ni = 0; ni < 4; ni++) {                                       \
            int nc = wn * 32 + ni * 8 + gid;                                   \
            bf2[ni][0] = __float_as_uint(BsC[ks + tig][nc]);                   \
            bf2[ni][1] = __float_as_uint(BsC[ks + tig + 4][nc]);               \
        }                                                                      \
        _Pragma("unroll")                                                      \
        for (int mi = 0; mi < 2; mi++)                                         \
            _Pragma("unroll")                                                  \
            for (int ni = 0; ni < 4; ni++)                                     \
                asm volatile(                                                  \
                    "mma.sync.aligned.m16n8k8.row.col.f32.tf32.tf32.f32 "      \
                    "{%0,%1,%2,%3}, {%4,%5,%6,%7}, {%8,%9}, {%0,%1,%2,%3};\n"  \
                    : "+f"(acc[mi][ni][0]), "+f"(acc[mi][ni][1]),              \
                      "+f"(acc[mi][ni][2]), "+f"(acc[mi][ni][3])               \
                    : "r"(af[mi][0]), "r"(af[mi][1]),                          \
                      "r"(af[mi][2]), "r"(af[mi][3]),                          \
                      "r"(bf2[ni][0]), "r"(bf2[ni][1]));                       \
    }

// ---------------------------------------------------------------------------
// QKV projection
// ---------------------------------------------------------------------------
__global__ void qkv_kernel(const float* __restrict__ x,
                           const float* __restrict__ Wq, const float* __restrict__ bq,
                           const float* __restrict__ Wk, const float* __restrict__ bk,
                           const float* __restrict__ Wv, const float* __restrict__ bv)
{
    __shared__ float As[2][BK][BM + PADF];
    __shared__ float Bs[2][BK][BN + PADF];

    const int j   = blockIdx.z;
    const int mat = j >> 1;
    const int n   = j & 1;
    const int o0  = blockIdx.x * BN;
    const int m0  = blockIdx.y * BM;

    const float* W    = (mat == 0) ? Wq : (mat == 1) ? Wk : Wv;
    const float* bias = (mat == 0) ? bq : (mat == 1) ? bk : bv;
    float* out        = (mat == 0) ? g_Q : (mat == 1) ? g_K : g_V;

    const float* A  = x + (size_t)m0 * Ee + n * Hh;              // lda = Ee
    const float* Bm = W + (size_t)n * Hh * Hh + (size_t)o0 * Hh; // ldb = Hh

    const int tid = threadIdx.x;
    const int lane = tid & 31;
    const int wm = (tid >> 5) >> 1, wn = (tid >> 5) & 1;
    const int gid = lane >> 2, tig = lane & 3;
    const int lr = tid >> 2, lk = (tid & 3) * 4;

    float acc[2][4][4] = {};

    {
        float4 a0 = *(const float4*)(A + (size_t)lr * Ee + lk);
        float4 a1 = *(const float4*)(A + (size_t)(lr + 64) * Ee + lk);
        float4 b0 = *(const float4*)(Bm + (size_t)lr * Hh + lk);
        As[0][lk+0][lr] = f2tf32(a0.x); As[0][lk+1][lr] = f2tf32(a0.y); As[0][lk+2][lr] = f2tf32(a0.z); As[0][lk+3][lr] = f2tf32(a0.w);
        As[0][lk+0][lr+64] = f2tf32(a1.x); As[0][lk+1][lr+64] = f2tf32(a1.y); As[0][lk+2][lr+64] = f2tf32(a1.z); As[0][lk+3][lr+64] = f2tf32(a1.w);
        Bs[0][lk+0][lr] = f2tf32(b0.x); Bs[0][lk+1][lr] = f2tf32(b0.y); Bs[0][lk+2][lr] = f2tf32(b0.z); Bs[0][lk+3][lr] = f2tf32(b0.w);
    }
    __syncthreads();

    const int T = Hh / BK;
    int cur = 0;
    for (int t = 0; t < T; t++) {
        float4 pa0, pa1, pb;
        if (t + 1 < T) {
            int k0 = (t + 1) * BK;
            pa0 = *(const float4*)(A + (size_t)lr * Ee + k0 + lk);
            pa1 = *(const float4*)(A + (size_t)(lr + 64) * Ee + k0 + lk);
            pb  = *(const float4*)(Bm + (size_t)lr * Hh + k0 + lk);
        }
        MMA_TILE(As[cur], Bs[cur]);
        if (t + 1 < T) {
            int nx = cur ^ 1;
            As[nx][lk+0][lr] = f2tf32(pa0.x); As[nx][lk+1][lr] = f2tf32(pa0.y); As[nx][lk+2][lr] = f2tf32(pa0.z); As[nx][lk+3][lr] = f2tf32(pa0.w);
            As[nx][lk+0][lr+64] = f2tf32(pa1.x); As[nx][lk+1][lr+64] = f2tf32(pa1.y); As[nx][lk+2][lr+64] = f2tf32(pa1.z); As[nx][lk+3][lr+64] = f2tf32(pa1.w);
            Bs[nx][lk+0][lr] = f2tf32(pb.x); Bs[nx][lk+1][lr] = f2tf32(pb.y); Bs[nx][lk+2][lr] = f2tf32(pb.z); Bs[nx][lk+3][lr] = f2tf32(pb.w);
            __syncthreads();
            cur = nx;
        }
    }

#pragma unroll
    for (int mi = 0; mi < 2; mi++) {
#pragma unroll
        for (int half = 0; half < 2; half++) {
            int m = m0 + wm * 32 + mi * 16 + gid + half * 8;
            int b = m / Ss, s = m % Ss;
            size_t rowbase = ((size_t)(b * 2 + n) * Ss + s) * Hh;
#pragma unroll
            for (int ni = 0; ni < 4; ni++) {
                int o = o0 + wn * 32 + ni * 8 + tig * 2;
                float c0 = acc[mi][ni][half * 2 + 0] + bias[n * Hh + o];
                float c1 = acc[mi][ni][half * 2 + 1] + bias[n * Hh + o + 1];
                *(float2*)&out[rowbase + o] = make_float2(c0, c1);
            }
        }
    }
}

// ---------------------------------------------------------------------------
// scores: blocks entirely above diagonal skipped (t0 >= s0 + BM)
// ---------------------------------------------------------------------------
__global__ void scores_kernel(const int* __restrict__ maskedp)
{
    __shared__ float As[2][BK][BM + PADF];
    __shared__ float Bs[2][BK][BN + PADF];

    const int g  = blockIdx.z;
    const int t0 = blockIdx.x * BN;
    const int s0 = blockIdx.y * BM;
    const int masked = *maskedp;

    if (masked && t0 >= s0 + BM) return;

    float* out = g_Sc + (size_t)g * Ss * Ss;
    const float* A  = g_Q + (size_t)g * Ss * Hh + (size_t)s0 * Hh;
    const float* Bm = g_K + (size_t)g * Ss * Hh + (size_t)t0 * Hh;

    const int tid = threadIdx.x;
    const int lane = tid & 31;
    const int wm = (tid >> 5) >> 1, wn = (tid >> 5) & 1;
    const int gid = lane >> 2, tig = lane & 3;
    const int lr = tid >> 2, lk = (tid & 3) * 4;

    float acc[2][4][4] = {};

    {
        float4 a0 = *(const float4*)(A + (size_t)lr * Hh + lk);
        float4 a1 = *(const float4*)(A + (size_t)(lr + 64) * Hh + lk);
        float4 b0 = *(const float4*)(Bm + (size_t)lr * Hh + lk);
        As[0][lk+0][lr] = f2tf32(a0.x); As[0][lk+1][lr] = f2tf32(a0.y); As[0][lk+2][lr] = f2tf32(a0.z); As[0][lk+3][lr] = f2tf32(a0.w);
        As[0][lk+0][lr+64] = f2tf32(a1.x); As[0][lk+1][lr+64] = f2tf32(a1.y); As[0][lk+2][lr+64] = f2tf32(a1.z); As[0][lk+3][lr+64] = f2tf32(a1.w);
        Bs[0][lk+0][lr] = f2tf32(b0.x); Bs[0][lk+1][lr] = f2tf32(b0.y); Bs[0][lk+2][lr] = f2tf32(b0.z); Bs[0][lk+3][lr] = f2tf32(b0.w);
    }
    __syncthreads();

    const int T = Hh / BK;
    int cur = 0;
    for (int t = 0; t < T; t++) {
        float4 pa0, pa1, pb;
        if (t + 1 < T) {
            int k0 = (t + 1) * BK;
            pa0 = *(const float4*)(A + (size_t)lr * Hh + k0 + lk);
            pa1 = *(const float4*)(A + (size_t)(lr + 64) * Hh + k0 + lk);
            pb  = *(const float4*)(Bm + (size_t)lr * Hh + k0 + lk);
        }
        MMA_TILE(As[cur], Bs[cur]);
        if (t + 1 < T) {
            int nx = cur ^ 1;
            As[nx][lk+0][lr] = f2tf32(pa0.x); As[nx][lk+1][lr] = f2tf32(pa0.y); As[nx][lk+2][lr] = f2tf32(pa0.z); As[nx][lk+3][lr] = f2tf32(pa0.w);
            As[nx][lk+0][lr+64] = f2tf32(pa1.x); As[nx][lk+1][lr+64] = f2tf32(pa1.y); As[nx][lk+2][lr+64] = f2tf32(pa1.z); As[nx][lk+3][lr+64] = f2tf32(pa1.w);
            Bs[nx][lk+0][lr] = f2tf32(pb.x); Bs[nx][lk+1][lr] = f2tf32(pb.y); Bs[nx][lk+2][lr] = f2tf32(pb.z); Bs[nx][lk+3][lr] = f2tf32(pb.w);
            __syncthreads();
            cur = nx;
        }
    }

    const float scale = 0.044194173824159216f;  // 1/sqrt(512)
#pragma unroll
    for (int mi = 0; mi < 2; mi++) {
#pragma unroll
        for (int half = 0; half < 2; half++) {
            int s = s0 + wm * 32 + mi * 16 + gid + half * 8;
#pragma unroll
            for (int ni = 0; ni < 4; ni++) {
                int tt = t0 + wn * 32 + ni * 8 + tig * 2;
                float c0 = acc[mi][ni][half * 2 + 0] * scale;
                float c1 = acc[mi][ni][half * 2 + 1] * scale;
                if (masked && tt > s)     c0 = -3.0e38f;
                if (masked && tt + 1 > s) c1 = -3.0e38f;
                *(float2*)&out[(size_t)s * Ss + tt] = make_float2(c0, c1);
            }
        }
    }
}

// ---------------------------------------------------------------------------
// Row softmax, causal limit rounded to BM=128 boundary
// ---------------------------------------------------------------------------
__global__ void softmax_kernel(const int* __restrict__ maskedp)
{
    const int row = blockIdx.x;
    const int s = row & (Ss - 1);
    const int limit = (*maskedp) ? (((s >> 7) + 1) << 7) : Ss;

    float* r = g_Sc + (size_t)row * Ss;
    __shared__ float red[8];
    const int tid = threadIdx.x;           // 256 threads
    const int lane = tid & 31, warp = tid >> 5;

    float m = -3.4e38f;
    for (int i = tid; i < limit; i += 256) m = fmaxf(m, r[i]);
#pragma unroll
    for (int off = 16; off > 0; off >>= 1)
        m = fmaxf(m, __shfl_xor_sync(0xFFFFFFFFu, m, off));
    if (lane == 0) red[warp] = m;
    __syncthreads();
    if (warp == 0) {
        float v = (lane < 8) ? red[lane] : -3.4e38f;
#pragma unroll
        for (int off = 4; off > 0; off >>= 1)
            v = fmaxf(v, __shfl_xor_sync(0xFFFFFFFFu, v, off));
        if (lane == 0) red[0] = v;
    }
    __syncthreads();
    m = red[0];
    __syncthreads();

    float sum = 0.f;
    for (int i = tid; i < limit; i += 256) {
        float e = __expf(r[i] - m);
        r[i] = e;
        sum += e;
    }
#pragma unroll
    for (int off = 16; off > 0; off >>= 1)
        sum += __shfl_xor_sync(0xFFFFFFFFu, sum, off);
    if (lane == 0) red[warp] = sum;
    __syncthreads();
    if (warp == 0) {
        float v = (lane < 8) ? red[lane] : 0.f;
#pragma unroll
        for (int off = 4; off > 0; off >>= 1)
            v += __shfl_xor_sync(0xFFFFFFFFu, v, off);
        if (lane == 0) red[0] = v;
    }
    __syncthreads();
    float inv = 1.0f / red[0];
    for (int i = tid; i < limit; i += 256) r[i] *= inv;
}

// ---------------------------------------------------------------------------
// PV: NN GEMM, causal K-limit s0+BM
// ---------------------------------------------------------------------------
__global__ void pv_kernel(const int* __restrict__ maskedp)
{
    __shared__ float As[2][BK][BM + PADF];
    __shared__ float Bs[2][BK][BN + PADF];

    const int g  = blockIdx.z;
    const int h0 = blockIdx.x * BN;
    const int s0 = blockIdx.y * BM;
    const int tid = threadIdx.x;

    const float* A  = g_Sc + (size_t)g * Ss * Ss + (size_t)s0 * Ss;  // lda = Ss
    const float* Bm = g_V + (size_t)g * Ss * Hh;                      // ldb = Hh

    const int kmax = (*maskedp) ? (s0 + BM) : Ss;

    const int lane = tid & 31;
    const int wm = (tid >> 5) >> 1, wn = (tid >> 5) & 1;
    const int gid = lane >> 2, tig = lane & 3;
    const int lr = tid >> 2, lk = (tid & 3) * 4;
    const int bk = tid >> 4, bn = (tid & 15) * 4;

    float acc[2][4][4] = {};

    {
        float4 a0 = *(const float4*)(A + (size_t)lr * Ss + lk);
        float4 a1 = *(const float4*)(A + (size_t)(lr + 64) * Ss + lk);
        As[0][lk+0][lr] = f2tf32(a0.x); As[0][lk+1][lr] = f2tf32(a0.y); As[0][lk+2][lr] = f2tf32(a0.z); As[0][lk+3][lr] = f2tf32(a0.w);
        As[0][lk+0][lr+64] = f2tf32(a1.x); As[0][lk+1][lr+64] = f2tf32(a1.y); As[0][lk+2][lr+64] = f2tf32(a1.z); As[0][lk+3][lr+64] = f2tf32(a1.w);
        float4 b0 = *(const float4*)(Bm + (size_t)bk * Hh + h0 + bn);
        Bs[0][bk][bn+0] = f2tf32(b0.x); Bs[0][bk][bn+1] = f2tf32(b0.y);
        Bs[0][bk][bn+2] = f2tf32(b0.z); Bs[0][bk][bn+3] = f2tf32(b0.w);
    }
    __syncthreads();

    const int T = kmax / BK;
    int cur = 0;
    for (int t = 0; t < T; t++) {
        float4 pa0, pa1, pb;
        if (t + 1 < T) {
            int k0 = (t + 1) * BK;
            pa0 = *(const float4*)(A + (size_t)lr * Ss + k0 + lk);
            pa1 = *(const float4*)(A + (size_t)(lr + 64) * Ss + k0 + lk);
            pb  = *(const float4*)(Bm + (size_t)(k0 + bk) * Hh + h0 + bn);
        }
        MMA_TILE(As[cur], Bs[cur]);
        if (t + 1 < T) {
            int nx = cur ^ 1;
            As[nx][lk+0][lr] = f2tf32(pa0.x); As[nx][lk+1][lr] = f2tf32(pa0.y); As[nx][lk+2][lr] = f2tf32(pa0.z); As[nx][lk+3][lr] = f2tf32(pa0.w);
            As[nx][lk+0][lr+64] = f2tf32(pa1.x); As[nx][lk+1][lr+64] = f2tf32(pa1.y); As[nx][lk+2][lr+64] = f2tf32(pa1.z); As[nx][lk+3][lr+64] = f2tf32(pa1.w);
            Bs[nx][bk][bn+0] = f2tf32(pb.x); Bs[nx][bk][bn+1] = f2tf32(pb.y);
            Bs[nx][bk][bn+2] = f2tf32(pb.z); Bs[nx][bk][bn+3] = f2tf32(pb.w);
            __syncthreads();
            cur = nx;
        }
    }

    const int b = g >> 1, n = g & 1;
#pragma unroll
    for (int mi = 0; mi < 2; mi++) {
#pragma unroll
        for (int half = 0; half < 2; half++) {
            int s = s0 + wm * 32 + mi * 16 + gid + half * 8;
            size_t rowbase = ((size_t)b * Ss + s) * Ee + n * Hh;
#pragma unroll
            for (int ni = 0; ni < 4; ni++) {
                int h = h0 + wn * 32 + ni * 8 + tig * 2;
                *(float2*)&g_O[rowbase + h] =
                    make_float2(acc[mi][ni][half * 2 + 0], acc[mi][ni][half * 2 + 1]);
            }
        }
    }
}

// ---------------------------------------------------------------------------
// Final projection (NT) + bias
// ---------------------------------------------------------------------------
__global__ void final_kernel(const float* __restrict__ Wf,
                             const float* __restrict__ bf,
                             float* __restrict__ y)
{
    __shared__ float As[2][BK][BM + PADF];
    __shared__ float Bs[2][BK][BN + PADF];

    const int o0 = blockIdx.x * BN;
    const int m0 = blockIdx.y * BM;
    const int tid = threadIdx.x;

    const float* A  = g_O + (size_t)m0 * Ee;   // lda = Ee
    const float* Bm = Wf + (size_t)o0 * Ee;    // ldb = Ee

    const int lane = tid & 31;
    const int wm = (tid >> 5) >> 1, wn = (tid >> 5) & 1;
    const int gid = lane >> 2, tig = lane & 3;
    const int lr = tid >> 2, lk = (tid & 3) * 4;

    float acc[2][4][4] = {};

    {
        float4 a0 = *(const float4*)(A + (size_t)lr * Ee + lk);
        float4 a1 = *(const float4*)(A + (size_t)(lr + 64) * Ee + lk);
        float4 b0 = *(const float4*)(Bm + (size_t)lr * Ee + lk);
        As[0][lk+0][lr] = f2tf32(a0.x); As[0][lk+1][lr] = f2tf32(a0.y); As[0][lk+2][lr] = f2tf32(a0.z); As[0][lk+3][lr] = f2tf32(a0.w);
        As[0][lk+0][lr+64] = f2tf32(a1.x); As[0][lk+1][lr+64] = f2tf32(a1.y); As[0][lk+2][lr+64] = f2tf32(a1.z); As[0][lk+3][lr+64] = f2tf32(a1.w);
        Bs[0][lk+0][lr] = f2tf32(b0.x); Bs[0][lk+1][lr] = f2tf32(b0.y); Bs[0][lk+2][lr] = f2tf32(b0.z); Bs[0][lk+3][lr] = f2tf32(b0.w);
    }
    __syncthreads();

    const int T = Ee / BK;
    int cur = 0;
    for (int t = 0; t < T; t++) {
        float4 pa0, pa1, pb;
        if (t + 1 < T) {
            int k0 = (t + 1) * BK;
            pa0 = *(const float4*)(A + (size_t)lr * Ee + k0 + lk);
            pa1 = *(const float4*)(A + (size_t)(lr + 64) * Ee + k0 + lk);
            pb  = *(const float4*)(Bm + (size_t)lr * Ee + k0 + lk);
        }
        MMA_TILE(As[cur], Bs[cur]);
        if (t + 1 < T) {
            int nx = cur ^ 1;
            As[nx][lk+0][lr] = f2tf32(pa0.x); As[nx][lk+1][lr] = f2tf32(pa0.y); As[nx][lk+2][lr] = f2tf32(pa0.z); As[nx][lk+3][lr] = f2tf32(pa0.w);
            As[nx][lk+0][lr+64] = f2tf32(pa1.x); As[nx][lk+1][lr+64] = f2tf32(pa1.y); As[nx][lk+2][lr+64] = f2tf32(pa1.z); As[nx][lk+3][lr+64] = f2tf32(pa1.w);
            Bs[nx][lk+0][lr] = f2tf32(pb.x); Bs[nx][lk+1][lr] = f2tf32(pb.y); Bs[nx][lk+2][lr] = f2tf32(pb.z); Bs[nx][lk+3][lr] = f2tf32(pb.w);
            __syncthreads();
            cur = nx;
        }
    }

#pragma unroll
    for (int mi = 0; mi < 2; mi++) {
#pragma unroll
        for (int half = 0; half < 2; half++) {
            int m = m0 + wm * 32 + mi * 16 + gid + half * 8;
#pragma unroll
            for (int ni = 0; ni < 4; ni++) {
                int o = o0 + wn * 32 + ni * 8 + tig * 2;
                float c0 = acc[mi][ni][half * 2 + 0] + bf[o];
                float c1 = acc[mi][ni][half * 2 + 1] + bf[o + 1];
                *(float2*)&y[(size_t)m * Ee + o] = make_float2(c0, c1);
            }
        }
    }
}

// ---------------------------------------------------------------------------
extern "C" void kernel_launch(void* const* d_in, const int* in_sizes, int n_in,
                              void* d_out, int out_size)
{
    const float* x  = (const float*)d_in[0];
    const float* Wq = (const float*)d_in[1];
    const float* bq = (const float*)d_in[2];
    const float* Wk = (const float*)d_in[3];
    const float* bk = (const float*)d_in[4];
    const float* Wv = (const float*)d_in[5];
    const float* bv = (const float*)d_in[6];
    const float* Wf = (const float*)d_in[7];
    const float* bf = (const float*)d_in[8];
    const int* masked = (const int*)d_in[9];
    float* y = (float*)d_out;

    const int M = Bb * Ss;  // 8192 tokens

    qkv_kernel<<<dim3(Hh / BN, M / BM, 6), 256>>>(x, Wq, bq, Wk, bk, Wv, bv);
    scores_kernel<<<dim3(Ss / BN, Ss / BM, NG), 256>>>(masked);
    softmax_kernel<<<NG * Ss, 256>>>(masked);
    pv_kernel<<<dim3(Hh / BN, Ss / BM, NG), 256>>>(masked);
    final_kernel<<<dim3(Ee / BN, M / BM), 256>>>(Wf, bf, y);
}